// round 1
// baseline (speedup 1.0000x reference)
#include <cuda_runtime.h>
#include <cstdint>

// Problem constants
#define TOKENS   131072      // 4 * 32 * 32 * 32
#define CDIM     64
#define KCODES   1024
#define HWD      32768       // 32*32*32
#define ZQ_SIZE  8388608     // 4*64*32768
// Output layout: [z_q (8388608) | loss (1) | perplexity (1) | indices (131072) | mean_dist (1)]
#define LOSS_OFF 8388608
#define PERP_OFF 8388609
#define IDX_OFF  8388610
#define MEAN_OFF 8519682

typedef unsigned long long u64;

// ---------- scratch (no allocations allowed) ----------
__device__ float g_e2[KCODES];    // ||e_k||^2
__device__ float g_esum[CDIM];    // sum_k e[k][c]
__device__ float g_zsum[CDIM];    // sum_n z[n][c]
__device__ float g_sz2;           // sum of all z^2
__device__ int   g_hist[KCODES];  // bincount of argmin indices

// ---------- packed f32x2 helpers (Blackwell dual-issue fp32) ----------
__device__ __forceinline__ u64 pack2(float x, float y) {
    u64 r;
    asm("mov.b64 %0, {%1, %2};" : "=l"(r) : "f"(x), "f"(y));
    return r;
}
__device__ __forceinline__ float2 unpack2(u64 v) {
    float2 f;
    asm("mov.b64 {%0, %1}, %2;" : "=f"(f.x), "=f"(f.y) : "l"(v));
    return f;
}
__device__ __forceinline__ void fma2(u64& d, u64 a, u64 b) {
    asm("fma.rn.f32x2 %0, %1, %2, %0;" : "+l"(d) : "l"(a), "l"(b));
}

// ---------- init: zero accumulators ----------
__global__ void vq_init() {
    int t = threadIdx.x;            // 1024 threads
    g_hist[t] = 0;
    if (t < CDIM) g_zsum[t] = 0.0f;
    if (t == 0)   g_sz2 = 0.0f;
}

// ---------- per-code squared norms ----------
__global__ void vq_e2(const float* __restrict__ emb) {
    int k = blockIdx.x * 256 + threadIdx.x;   // 4 blocks x 256
    const float4* e4 = (const float4*)emb;
    float s = 0.0f;
#pragma unroll
    for (int j = 0; j < 16; j++) {
        float4 v = e4[k * 16 + j];
        s += v.x * v.x + v.y * v.y + v.z * v.z + v.w * v.w;
    }
    g_e2[k] = s;
}

// ---------- per-channel codebook sums ----------
__global__ void vq_esum(const float* __restrict__ emb) {
    int c = blockIdx.x;                       // 64 blocks x 256
    float s = 0.0f;
    for (int k = threadIdx.x; k < KCODES; k += 256) s += emb[k * CDIM + c];
#pragma unroll
    for (int o = 16; o; o >>= 1) s += __shfl_down_sync(0xffffffffu, s, o);
    __shared__ float sw[8];
    if ((threadIdx.x & 31) == 0) sw[threadIdx.x >> 5] = s;
    __syncthreads();
    if (threadIdx.x == 0) {
        float t = 0.0f;
        for (int w = 0; w < 8; w++) t += sw[w];
        g_esum[c] = t;
    }
}

// ---------- z statistics: sum z^2 (scalar) and per-channel sum z ----------
__global__ void vq_statsz(const float* __restrict__ z) {
    __shared__ float sh_zs[CDIM];
    __shared__ float sh_s2[8];
    int tid = threadIdx.x;
    if (tid < CDIM) sh_zs[tid] = 0.0f;
    __syncthreads();

    const float4* z4 = (const float4*)z;
    float s2 = 0.0f;
    int lane = tid & 31, wid = tid >> 5;
#pragma unroll 4
    for (int m = 0; m < 32; m++) {
        int i4 = blockIdx.x * 256 + tid + m * 65536;   // 256 blocks cover 2097152 float4s
        float4 v = z4[i4];
        s2 += v.x * v.x + v.y * v.y + v.z * v.z + v.w * v.w;
        float vs = v.x + v.y + v.z + v.w;
#pragma unroll
        for (int o = 16; o; o >>= 1) vs += __shfl_down_sync(0xffffffffu, vs, o);
        if (lane == 0) atomicAdd(&sh_zs[(i4 >> 13) & 63], vs);  // warp-uniform channel
    }
#pragma unroll
    for (int o = 16; o; o >>= 1) s2 += __shfl_down_sync(0xffffffffu, s2, o);
    if (lane == 0) sh_s2[wid] = s2;
    __syncthreads();
    if (tid == 0) {
        float t = 0.0f;
        for (int w = 0; w < 8; w++) t += sh_s2[w];
        atomicAdd(&g_sz2, t);
    }
    if (tid < CDIM) atomicAdd(&g_zsum[tid], sh_zs[tid]);
}

// ---------- main: fused argmin-distance GEMM + gather + histogram ----------
// 256 blocks x 256 threads, 2 tokens/thread (512 tokens/block).
__global__ void __launch_bounds__(256, 1)
vq_main(const float* __restrict__ z, const float* __restrict__ emb,
        float* __restrict__ out) {
    __shared__ float sh_e[128 * 64];   // 32 KB codebook chunk
    __shared__ float sh_e2[128];
    __shared__ int   sh_hist[KCODES];  // 4 KB

    int tid = threadIdx.x;
    int blk = blockIdx.x;
    int n0  = blk * 512 + tid;         // second token = n0 + 256 (same b region)
    int b   = n0 >> 15;
    int hwd0 = n0 & 32767;
    const float* zb = z + (size_t)b * CDIM * HWD;

    // Load both tokens' 64-dim vectors into packed registers (coalesced per c)
    u64 za[32], zc[32];
#pragma unroll
    for (int j = 0; j < 32; j++) {
        float a0 = zb[(2 * j) * HWD + hwd0];
        float a1 = zb[(2 * j + 1) * HWD + hwd0];
        float c0 = zb[(2 * j) * HWD + hwd0 + 256];
        float c1 = zb[(2 * j + 1) * HWD + hwd0 + 256];
        za[j] = pack2(a0, a1);
        zc[j] = pack2(c0, c1);
    }
    for (int t = tid; t < KCODES; t += 256) sh_hist[t] = 0;

    float mina = 3.4e38f, minb = 3.4e38f;
    int   ia = 0, ibx = 0;
    const float4* e4 = (const float4*)emb;

    for (int ch = 0; ch < 8; ch++) {
        __syncthreads();
        int base = ch * 128;
        float4* se4 = (float4*)sh_e;
#pragma unroll
        for (int t = 0; t < 8; t++)
            se4[tid + t * 256] = e4[base * 16 + tid + t * 256];
        if (tid < 128) sh_e2[tid] = g_e2[base + tid];
        __syncthreads();

        for (int kk = 0; kk < 128; kk++) {
            const ulonglong2* ep = (const ulonglong2*)(sh_e + kk * 64);
            u64 aa0 = 0ull, aa1 = 0ull, ab0 = 0ull, ab1 = 0ull;
#pragma unroll
            for (int j = 0; j < 16; j++) {
                ulonglong2 ev = ep[j];
                fma2(aa0, za[2 * j],     ev.x);
                fma2(aa1, za[2 * j + 1], ev.y);
                fma2(ab0, zc[2 * j],     ev.x);
                fma2(ab1, zc[2 * j + 1], ev.y);
            }
            float2 fa0 = unpack2(aa0), fa1 = unpack2(aa1);
            float2 fb0 = unpack2(ab0), fb1 = unpack2(ab1);
            float dota = (fa0.x + fa0.y) + (fa1.x + fa1.y);
            float dotb = (fb0.x + fb0.y) + (fb1.x + fb1.y);
            float e2v = sh_e2[kk];
            float sa = fmaf(-2.0f, dota, e2v);
            float sb = fmaf(-2.0f, dotb, e2v);
            int kidx = base + kk;
            if (sa < mina) { mina = sa; ia  = kidx; }
            if (sb < minb) { minb = sb; ibx = kidx; }
        }
    }

    // indices (as float, reference returns int but output buffer is fp32)
    out[IDX_OFF + n0]       = (float)ia;
    out[IDX_OFF + n0 + 256] = (float)ibx;
    atomicAdd(&sh_hist[ia], 1);
    atomicAdd(&sh_hist[ibx], 1);

    // gather z_q = embedding[idx] into [b,c,h,w,d] layout (coalesced across warp per c)
    size_t ob = (size_t)b * CDIM * HWD;
#pragma unroll
    for (int j = 0; j < 16; j++) {
        float4 va = __ldg(&e4[ia * 16 + j]);
        float4 vb = __ldg(&e4[ibx * 16 + j]);
        out[ob + (size_t)(4 * j + 0) * HWD + hwd0] = va.x;
        out[ob + (size_t)(4 * j + 1) * HWD + hwd0] = va.y;
        out[ob + (size_t)(4 * j + 2) * HWD + hwd0] = va.z;
        out[ob + (size_t)(4 * j + 3) * HWD + hwd0] = va.w;
        out[ob + (size_t)(4 * j + 0) * HWD + hwd0 + 256] = vb.x;
        out[ob + (size_t)(4 * j + 1) * HWD + hwd0 + 256] = vb.y;
        out[ob + (size_t)(4 * j + 2) * HWD + hwd0 + 256] = vb.z;
        out[ob + (size_t)(4 * j + 3) * HWD + hwd0 + 256] = vb.w;
    }

    __syncthreads();
    for (int t = tid; t < KCODES; t += 256) {
        int h = sh_hist[t];
        if (h) atomicAdd(&g_hist[t], h);
    }
}

// ---------- finalize: perplexity + analytic mean(dist) + loss ----------
__global__ void vq_final(float* __restrict__ out) {
    int t = threadIdx.x;   // 1024 threads
    double e2  = (double)g_e2[t];
    double h   = (double)g_hist[t] * (1.0 / (double)TOKENS);
    double ent = -h * log(h + 1e-10);
    double dss = (t < CDIM) ? (double)g_zsum[t] * (double)g_esum[t] : 0.0;

    __shared__ double s1[32], s2[32], s3[32];
#pragma unroll
    for (int o = 16; o; o >>= 1) {
        e2  += __shfl_down_sync(0xffffffffu, e2,  o);
        ent += __shfl_down_sync(0xffffffffu, ent, o);
        dss += __shfl_down_sync(0xffffffffu, dss, o);
    }
    int w = t >> 5, l = t & 31;
    if (l == 0) { s1[w] = e2; s2[w] = ent; s3[w] = dss; }
    __syncthreads();
    if (t == 0) {
        double E2 = 0, EN = 0, DS = 0;
        for (int i = 0; i < 32; i++) { E2 += s1[i]; EN += s2[i]; DS += s3[i]; }
        out[LOSS_OFF] = 0.0f;
        out[PERP_OFF] = (float)exp(EN);
        double nt = (double)TOKENS, kk = (double)KCODES;
        // mean(dist) = (K*sum||z||^2 - 2*(sum z)·(sum e) + N*sum||e||^2) / (N*K)
        out[MEAN_OFF] = (float)((kk * (double)g_sz2 - 2.0 * DS + nt * E2) / (nt * kk));
    }
}

extern "C" void kernel_launch(void* const* d_in, const int* in_sizes, int n_in,
                              void* d_out, int out_size) {
    (void)in_sizes; (void)n_in; (void)out_size;
    const float* z   = (const float*)d_in[0];
    const float* emb = (const float*)d_in[1];
    float* out = (float*)d_out;

    vq_init  <<<1,   1024>>>();
    vq_e2    <<<4,   256 >>>(emb);
    vq_esum  <<<64,  256 >>>(emb);
    vq_statsz<<<256, 256 >>>(z);
    vq_main  <<<256, 256 >>>(z, emb, out);
    vq_final <<<1,   1024>>>(out);
}

// round 5
// speedup vs baseline: 1.5210x; 1.5210x over previous
#include <cuda_runtime.h>
#include <cuda_fp16.h>
#include <cstdint>
#include <math.h>

// ---------------- problem constants ----------------
#define TOKENS   131072      // 4 * 32 * 32 * 32
#define CDIM     64
#define KCODES   1024
#define HWD      32768
// out layout: [z_q (8388608) | loss | perplexity | indices (131072) | mean_dist]
#define LOSS_OFF 8388608
#define PERP_OFF 8388609
#define IDX_OFF  8388610
#define MEAN_OFF 8519682

typedef unsigned int u32;

// ---------------- global scratch (static, no allocs) ----------------
__device__ float g_e2[KCODES];          // ||e_k||^2
__device__ float g_esum[CDIM];          // sum_k e[k][c]
__device__ float g_zsum[CDIM];          // sum_n z[n][c]
__device__ float g_sz2;                 // sum all z^2
__device__ int   g_hist[KCODES];        // argmin bincount
// codebook split to fp16 hi/lo, rows padded to 72 channels (bank-conflict-free)
__device__ __align__(16) __half g_Bh[KCODES * 72];
__device__ __align__(16) __half g_Bl[KCODES * 72];

// ---------------- helpers ----------------
__device__ __forceinline__ float warp_red(float v) {
#pragma unroll
    for (int o = 16; o; o >>= 1) v += __shfl_down_sync(0xffffffffu, v, o);
    return v;
}
__device__ __forceinline__ u32 split_pack(float x0, float x1, u32& lo) {
    __half h0 = __float2half_rn(x0), h1 = __float2half_rn(x1);
    __half l0 = __float2half_rn(x0 - __half2float(h0));
    __half l1 = __float2half_rn(x1 - __half2float(h1));
    __half2 hl = __halves2half2(l0, l1);
    lo = *reinterpret_cast<u32*>(&hl);
    __half2 hh = __halves2half2(h0, h1);
    return *reinterpret_cast<u32*>(&hh);
}
// m16n8k16 row.col f16 -> f32 accumulate (HMMA)
__device__ __forceinline__ void mma16816(float d[4], const u32 a[4], const u32 b[2]) {
    asm("mma.sync.aligned.m16n8k16.row.col.f32.f16.f16.f32 "
        "{%0,%1,%2,%3}, {%4,%5,%6,%7}, {%8,%9}, {%0,%1,%2,%3};"
        : "+f"(d[0]), "+f"(d[1]), "+f"(d[2]), "+f"(d[3])
        : "r"(a[0]), "r"(a[1]), "r"(a[2]), "r"(a[3]), "r"(b[0]), "r"(b[1]));
}

// exact fp32 distance with ROUND-1 accumulation order (empirically matches reference):
// 4 accumulators by channel mod 4, merged (A0+A1)+(A2+A3), dist = fma(-2, dot, e2)
__device__ __forceinline__ float exact_dist(const float* __restrict__ zcol, int apad,
                                            const float4* __restrict__ e4, int code) {
    float A0 = 0.0f, A1 = 0.0f, A2 = 0.0f, A3 = 0.0f;
#pragma unroll
    for (int c4 = 0; c4 < 16; c4++) {
        float4 e = __ldg(&e4[code * 16 + c4]);
        A0 = fmaf(zcol[(4 * c4 + 0) * apad], e.x, A0);
        A1 = fmaf(zcol[(4 * c4 + 1) * apad], e.y, A1);
        A2 = fmaf(zcol[(4 * c4 + 2) * apad], e.z, A2);
        A3 = fmaf(zcol[(4 * c4 + 3) * apad], e.w, A3);
    }
    float dot = (A0 + A1) + (A2 + A3);
    return fmaf(-2.0f, dot, g_e2[code]);
}

// ---------------- init ----------------
__global__ void vq_init() {
    int t = threadIdx.x;            // 1024 threads
    g_hist[t] = 0;
    if (t < CDIM) g_zsum[t] = 0.0f;
    if (t == 0)   g_sz2 = 0.0f;
}

// ---------------- per-code squared norms (identical to round-1) ----------------
__global__ void vq_e2(const float* __restrict__ emb) {
    int k = blockIdx.x * 256 + threadIdx.x;
    const float4* e4 = (const float4*)emb;
    float s = 0.0f;
#pragma unroll
    for (int j = 0; j < 16; j++) {
        float4 v = e4[k * 16 + j];
        s += v.x * v.x + v.y * v.y + v.z * v.z + v.w * v.w;
    }
    g_e2[k] = s;
}

// ---------------- per-channel codebook sums ----------------
__global__ void vq_esum(const float* __restrict__ emb) {
    int c = blockIdx.x;
    float s = 0.0f;
    for (int k = threadIdx.x; k < KCODES; k += 256) s += emb[k * CDIM + c];
    s = warp_red(s);
    __shared__ float sw[8];
    if ((threadIdx.x & 31) == 0) sw[threadIdx.x >> 5] = s;
    __syncthreads();
    if (threadIdx.x == 0) {
        float t = 0.0f;
        for (int w = 0; w < 8; w++) t += sw[w];
        g_esum[c] = t;
    }
}

// ---------------- codebook -> fp16 hi/lo, padded rows ----------------
__global__ void vq_prepB(const float* __restrict__ emb) {
    int i = blockIdx.x * 256 + threadIdx.x;   // 288 blocks: 1024*72 = 73728
    int code = i / 72, ch = i % 72;
    float x = (ch < CDIM) ? emb[code * CDIM + ch] : 0.0f;
    __half h = __float2half_rn(x);
    g_Bh[i] = h;
    g_Bl[i] = __float2half_rn(x - __half2float(h));
}

// ---------------- main: fp16 hi/lo mma GEMM + top-2 + gap-gated exact re-rank ----------------
// 512 CTAs x 256 threads; CTA = 256 tokens (8 warps x 32), loop 8 x 128-code chunks.
#define APADF 257
#define SM_ZF 0
#define SM_B   (64 * APADF * 4)              // 65792; 2 bufs x 36864 (hi 18432 + lo 18432)
#define SM_E2  (SM_B + 2 * 36864)            // 139520, 2 x 512
#define SM_I1  (SM_E2 + 1024)                // 140544
#define SM_I2  (SM_I1 + 1024)                // 141568
#define SM_GAP (SM_I2 + 1024)                // 142592
#define SM_S2  (SM_GAP + 1024)               // 143616
#define SMEM_TOTAL (SM_S2 + 32)              // 143648

__global__ void __launch_bounds__(256, 1)
vq_main_mma(const float* __restrict__ z, const float* __restrict__ emb,
            float* __restrict__ out) {
    extern __shared__ __align__(16) char sm[];
    float* sh_zf  = (float*)(sm + SM_ZF);     // fp32 A tile [c][token], padded
    float* pS2    = (float*)(sm + SM_S2);
    int*   sh_i1  = (int*)(sm + SM_I1);
    int*   sh_i2  = (int*)(sm + SM_I2);
    float* sh_gap = (float*)(sm + SM_GAP);

    const int tid = threadIdx.x;
    const int w = tid >> 5, l = tid & 31, g = l >> 2, t = l & 3;
    const int n0 = blockIdx.x * 256;
    const int b = n0 >> 15, hwb = n0 & 32767;

    const u32 bB  = (u32)__cvta_generic_to_shared(sm + SM_B);
    const u32 bE2 = (u32)__cvta_generic_to_shared(sm + SM_E2);

#define COPY_B(o, buf) do {                                                       \
        _Pragma("unroll")                                                         \
        for (int j = 0; j < 9; j++) {                                             \
            int f = tid + 256 * j;                                                \
            const float4* src = (f < 1152)                                        \
                ? ((const float4*)g_Bh) + (o) * 1152 + f                          \
                : ((const float4*)g_Bl) + (o) * 1152 + (f - 1152);                \
            u32 dst = bB + (buf) * 36864 + f * 16;                                \
            asm volatile("cp.async.cg.shared.global [%0], [%1], 16;"              \
                         :: "r"(dst), "l"(src));                                  \
        }                                                                         \
        if (tid < 128) {                                                          \
            u32 de = bE2 + (buf) * 512 + tid * 4;                                 \
            asm volatile("cp.async.ca.shared.global [%0], [%1], 4;"               \
                         :: "r"(de), "l"(g_e2 + (o) * 128 + tid));                \
        }                                                                         \
        asm volatile("cp.async.commit_group;");                                   \
    } while (0)

    COPY_B(0, 0);

    // ---- A load: 256 tokens x 64 ch, fp32 into smem, fold z^2 ----
    const float* zp = z + (size_t)b * CDIM * HWD + hwb + tid;
    float s2 = 0.0f;
#pragma unroll
    for (int c = 0; c < 64; c++) {
        float x = zp[(size_t)c * HWD];
        sh_zf[c * APADF + tid] = x;
        s2 = fmaf(x, x, s2);
    }
    s2 = warp_red(s2);
    if (l == 0) pS2[w] = s2;
    __syncthreads();
    if (tid == 0) {
        float v = 0.0f;
        for (int i = 0; i < 8; i++) v += pS2[i];
        atomicAdd(&g_sz2, v);
    }
    // per-channel z sums (fp32 exact from smem)
    {
        int c = tid >> 2, q = tid & 3;
        const float* pz = sh_zf + c * APADF + q * 64;
        float s = 0.0f;
#pragma unroll
        for (int i = 0; i < 64; i++) s += pz[i];
        atomicAdd(&g_zsum[c], s);
    }

    // ---- build A fragments (fp16 hi/lo) in registers, held for whole kernel ----
    u32 a_h[2][4][4], a_l[2][4][4];
    const int wb = w * 32;
#pragma unroll
    for (int m = 0; m < 2; m++) {
        int r0 = wb + m * 16 + g;
#pragma unroll
        for (int k = 0; k < 4; k++) {
            int c0 = k * 16 + 2 * t;
            a_h[m][k][0] = split_pack(sh_zf[c0 * APADF + r0],
                                      sh_zf[(c0 + 1) * APADF + r0], a_l[m][k][0]);
            a_h[m][k][1] = split_pack(sh_zf[c0 * APADF + r0 + 8],
                                      sh_zf[(c0 + 1) * APADF + r0 + 8], a_l[m][k][1]);
            a_h[m][k][2] = split_pack(sh_zf[(c0 + 8) * APADF + r0],
                                      sh_zf[(c0 + 9) * APADF + r0], a_l[m][k][2]);
            a_h[m][k][3] = split_pack(sh_zf[(c0 + 8) * APADF + r0 + 8],
                                      sh_zf[(c0 + 9) * APADF + r0 + 8], a_l[m][k][3]);
        }
    }

    // top-2 per chain (4 chains = 4 token rows per thread)
    float bd1[4] = {3.4e38f, 3.4e38f, 3.4e38f, 3.4e38f};
    float bd2[4] = {3.4e38f, 3.4e38f, 3.4e38f, 3.4e38f};
    int   bi1[4] = {0, 0, 0, 0}, bi2[4] = {0, 0, 0, 0};
#define UPD(s, d, c) do {                                                      \
        if ((d) < bd1[s]) { bd2[s] = bd1[s]; bi2[s] = bi1[s];                  \
                            bd1[s] = (d);    bi1[s] = (c); }                   \
        else if ((d) < bd2[s]) { bd2[s] = (d); bi2[s] = (c); }                 \
    } while (0)

    // ---- main loop: 8 chunks of 128 codes, double-buffered cp.async ----
#pragma unroll 1
    for (int o = 0; o < 8; o++) {
        asm volatile("cp.async.wait_group 0;" ::: "memory");
        __syncthreads();
        if (o < 7) COPY_B(o + 1, (o + 1) & 1);

        const __half* bh  = (const __half*)(sm + SM_B + (o & 1) * 36864);
        const __half* blp = bh + 9216;
        const float*  e2p = (const float*)(sm + SM_E2 + (o & 1) * 512);

#pragma unroll 1
        for (int sub = 0; sub < 8; sub++) {           // 16 codes per sub
            u32 Bh[2][4][2], Bl[2][4][2];
#pragma unroll
            for (int n = 0; n < 2; n++) {
                const __half* rb = bh  + (sub * 16 + n * 8 + g) * 72;
                const __half* rl = blp + (sub * 16 + n * 8 + g) * 72;
#pragma unroll
                for (int k = 0; k < 4; k++) {
                    Bh[n][k][0] = *(const u32*)(rb + k * 16 + 2 * t);
                    Bh[n][k][1] = *(const u32*)(rb + k * 16 + 2 * t + 8);
                    Bl[n][k][0] = *(const u32*)(rl + k * 16 + 2 * t);
                    Bl[n][k][1] = *(const u32*)(rl + k * 16 + 2 * t + 8);
                }
            }
            float D[2][2][4] = {};
#pragma unroll
            for (int k = 0; k < 4; k++)
#pragma unroll
                for (int n = 0; n < 2; n++)
#pragma unroll
                    for (int m = 0; m < 2; m++) {
                        mma16816(D[n][m], a_h[m][k], Bh[n][k]);   // hi*hi
                        mma16816(D[n][m], a_l[m][k], Bh[n][k]);   // lo*hi
                        mma16816(D[n][m], a_h[m][k], Bl[n][k]);   // hi*lo
                    }
            // dist = e2 - 2*dot, ascending code order per chain
#pragma unroll
            for (int n = 0; n < 2; n++) {
                int cl = sub * 16 + n * 8 + 2 * t;
                float e2a = e2p[cl], e2b = e2p[cl + 1];
                int cA = o * 128 + cl;
#pragma unroll
                for (int m = 0; m < 2; m++) {
                    float d0 = fmaf(-2.0f, D[n][m][0], e2a);
                    float d1 = fmaf(-2.0f, D[n][m][1], e2b);
                    float d2 = fmaf(-2.0f, D[n][m][2], e2a);
                    float d3 = fmaf(-2.0f, D[n][m][3], e2b);
                    UPD(m * 2, d0, cA);
                    UPD(m * 2, d1, cA + 1);
                    UPD(m * 2 + 1, d2, cA);
                    UPD(m * 2 + 1, d3, cA + 1);
                }
            }
        }
    }

    // ---- quad reduce: merge top-2 records across the 4 lanes of each row ----
#pragma unroll
    for (int s = 0; s < 4; s++) {
        float d1 = bd1[s], d2 = bd2[s];
        int   i1 = bi1[s], i2 = bi2[s];
#pragma unroll
        for (int off = 1; off <= 2; off <<= 1) {
            float od1 = __shfl_xor_sync(0xffffffffu, d1, off);
            int   oi1 = __shfl_xor_sync(0xffffffffu, i1, off);
            float od2 = __shfl_xor_sync(0xffffffffu, d2, off);
            int   oi2 = __shfl_xor_sync(0xffffffffu, i2, off);
            bool oBest = (od1 < d1) || (od1 == d1 && oi1 < i1);
            float w1 = oBest ? od1 : d1;  int wi1 = oBest ? oi1 : i1;
            float ld = oBest ? d1 : od1;  int li  = oBest ? i1 : oi1;   // loser's best
            float w2 = oBest ? od2 : d2;  int wi2 = oBest ? oi2 : i2;   // winner's 2nd
            bool l2 = (ld < w2) || (ld == w2 && li < wi2);
            d1 = w1; i1 = wi1;
            d2 = l2 ? ld : w2; i2 = l2 ? li : wi2;
        }
        if (t == 0) {
            int tok = wb + (s >> 1) * 16 + (s & 1) * 8 + g;
            sh_i1[tok] = i1;
            sh_i2[tok] = i2;
            sh_gap[tok] = d2 - d1;
        }
    }
    __syncthreads();

    // ---- gap-gated exact re-rank (round-1 accumulation order) ----
    const float4* e4 = (const float4*)emb;
    int idx = sh_i1[tid];
    if (sh_gap[tid] < 1e-3f) {       // ~1e-4 of tokens; approx error << 1e-3
        int j2 = sh_i2[tid];
        float distA = exact_dist(sh_zf + tid, APADF, e4, idx);
        float distB = exact_dist(sh_zf + tid, APADF, e4, j2);
        if (distB < distA || (distB == distA && j2 < idx)) idx = j2;
    }

    // ---- per-token outputs: index, histogram, coalesced z_q gather ----
    out[IDX_OFF + n0 + tid] = (float)idx;
    atomicAdd(&g_hist[idx], 1);

    float* ob = out + (size_t)b * CDIM * HWD + hwb + tid;
#pragma unroll
    for (int j = 0; j < 16; j++) {
        float4 v = __ldg(&e4[idx * 16 + j]);
        ob[(size_t)(4 * j + 0) * HWD] = v.x;
        ob[(size_t)(4 * j + 1) * HWD] = v.y;
        ob[(size_t)(4 * j + 2) * HWD] = v.z;
        ob[(size_t)(4 * j + 3) * HWD] = v.w;
    }
#undef COPY_B
#undef UPD
}

// ---------------- finalize: perplexity + analytic mean(dist) ----------------
__global__ void vq_final(float* __restrict__ out) {
    int t = threadIdx.x;   // 1024 threads
    double e2  = (double)g_e2[t];
    double h   = (double)g_hist[t] * (1.0 / (double)TOKENS);
    double ent = -h * log(h + 1e-10);
    double dss = (t < CDIM) ? (double)g_zsum[t] * (double)g_esum[t] : 0.0;

    __shared__ double s1[32], s2[32], s3[32];
#pragma unroll
    for (int o = 16; o; o >>= 1) {
        e2  += __shfl_down_sync(0xffffffffu, e2,  o);
        ent += __shfl_down_sync(0xffffffffu, ent, o);
        dss += __shfl_down_sync(0xffffffffu, dss, o);
    }
    int w = t >> 5, l = t & 31;
    if (l == 0) { s1[w] = e2; s2[w] = ent; s3[w] = dss; }
    __syncthreads();
    if (t == 0) {
        double E2 = 0, EN = 0, DS = 0;
        for (int i = 0; i < 32; i++) { E2 += s1[i]; EN += s2[i]; DS += s3[i]; }
        out[LOSS_OFF] = 0.0f;
        out[PERP_OFF] = (float)exp(EN);
        double nt = (double)TOKENS, kk = (double)KCODES;
        out[MEAN_OFF] = (float)((kk * (double)g_sz2 - 2.0 * DS + nt * E2) / (nt * kk));
    }
}

extern "C" void kernel_launch(void* const* d_in, const int* in_sizes, int n_in,
                              void* d_out, int out_size) {
    (void)in_sizes; (void)n_in; (void)out_size;
    const float* z   = (const float*)d_in[0];
    const float* emb = (const float*)d_in[1];
    float* out = (float*)d_out;

    cudaFuncSetAttribute(vq_main_mma, cudaFuncAttributeMaxDynamicSharedMemorySize, SMEM_TOTAL);

    vq_init    <<<1,   1024>>>();
    vq_e2      <<<4,   256 >>>(emb);
    vq_esum    <<<64,  256 >>>(emb);
    vq_prepB   <<<288, 256 >>>(emb);
    vq_main_mma<<<512, 256, SMEM_TOTAL>>>(z, emb, out);
    vq_final   <<<1,   1024>>>(out);
}

// round 6
// speedup vs baseline: 2.8350x; 1.8639x over previous
#include <cuda_runtime.h>
#include <cuda_fp16.h>
#include <cstdint>
#include <math.h>

// ---------------- problem constants ----------------
#define TOKENS   131072      // 4 * 32 * 32 * 32
#define CDIM     64
#define KCODES   1024
#define HWD      32768
// out layout: [z_q (8388608) | loss | perplexity | indices (131072) | mean_dist]
#define LOSS_OFF 8388608
#define PERP_OFF 8388609
#define IDX_OFF  8388610
#define MEAN_OFF 8519682

typedef unsigned int u32;
typedef unsigned long long u64;

// ---------------- global scratch (static, no allocs) ----------------
__device__ float g_e2[KCODES];          // ||e_k||^2
__device__ float g_esum[CDIM];          // sum_k e[k][c]
__device__ float g_zsum[CDIM];          // sum_n z[n][c]
__device__ float g_sz2;                 // sum all z^2
__device__ int   g_hist[KCODES];        // argmin bincount
// codebook fp16 (hi only), rows padded to 72 channels (bank-conflict-free)
__device__ __align__(16) __half g_Bh[KCODES * 72];

// ---------------- helpers ----------------
__device__ __forceinline__ float warp_red(float v) {
#pragma unroll
    for (int o = 16; o; o >>= 1) v += __shfl_down_sync(0xffffffffu, v, o);
    return v;
}
__device__ __forceinline__ u32 pack_h2(float x0, float x1) {
    __half2 h = __halves2half2(__float2half_rn(x0), __float2half_rn(x1));
    return *reinterpret_cast<u32*>(&h);
}
// m16n8k16 row.col f16 -> f32 accumulate (HMMA)
__device__ __forceinline__ void mma16816(float d[4], const u32 a[4], const u32 b[2]) {
    asm("mma.sync.aligned.m16n8k16.row.col.f32.f16.f16.f32 "
        "{%0,%1,%2,%3}, {%4,%5,%6,%7}, {%8,%9}, {%0,%1,%2,%3};"
        : "+f"(d[0]), "+f"(d[1]), "+f"(d[2]), "+f"(d[3])
        : "r"(a[0]), "r"(a[1]), "r"(a[2]), "r"(a[3]), "r"(b[0]), "r"(b[1]));
}
// sortable float key (ascending float -> ascending u32)
__device__ __forceinline__ u32 fkey(float f) {
    u32 b = __float_as_uint(f);
    return (b & 0x80000000u) ? ~b : (b | 0x80000000u);
}
__device__ __forceinline__ float fdec(u32 k) {
    return (k >> 31) ? __uint_as_float(k & 0x7FFFFFFFu) : __uint_as_float(~k);
}
__device__ __forceinline__ u64 u64min(u64 a, u64 b) { return a < b ? a : b; }
__device__ __forceinline__ u64 u64max(u64 a, u64 b) { return a > b ? a : b; }

// exact fp32 distance with ROUND-1 accumulation order (empirically matches reference):
// 4 accumulators by channel mod 4, merged (A0+A1)+(A2+A3), dist = fma(-2, dot, e2)
__device__ __forceinline__ float exact_dist(const float* __restrict__ zcol, int apad,
                                            const float4* __restrict__ e4, int code) {
    float A0 = 0.0f, A1 = 0.0f, A2 = 0.0f, A3 = 0.0f;
#pragma unroll
    for (int c4 = 0; c4 < 16; c4++) {
        float4 e = __ldg(&e4[code * 16 + c4]);
        A0 = fmaf(zcol[(4 * c4 + 0) * apad], e.x, A0);
        A1 = fmaf(zcol[(4 * c4 + 1) * apad], e.y, A1);
        A2 = fmaf(zcol[(4 * c4 + 2) * apad], e.z, A2);
        A3 = fmaf(zcol[(4 * c4 + 3) * apad], e.w, A3);
    }
    float dot = (A0 + A1) + (A2 + A3);
    return fmaf(-2.0f, dot, g_e2[code]);
}

// ---------------- launch 1: init ----------------
__global__ void vq_init() {
    int t = threadIdx.x;            // 1024 threads
    g_hist[t] = 0;
    if (t < CDIM) g_zsum[t] = 0.0f;
    if (t == 0)   g_sz2 = 0.0f;
}

// ---------------- launch 2: e2 (blocks 0-3) + esum (blocks 4-67) ----------------
__global__ void vq_prep1(const float* __restrict__ emb) {
    if (blockIdx.x < 4) {
        int k = blockIdx.x * 256 + threadIdx.x;
        const float4* e4 = (const float4*)emb;
        float s = 0.0f;
#pragma unroll
        for (int j = 0; j < 16; j++) {
            float4 v = e4[k * 16 + j];
            s += v.x * v.x + v.y * v.y + v.z * v.z + v.w * v.w;
        }
        g_e2[k] = s;
    } else {
        int c = blockIdx.x - 4;
        float s = 0.0f;
        for (int k = threadIdx.x; k < KCODES; k += 256) s += emb[k * CDIM + c];
        s = warp_red(s);
        __shared__ float sw[8];
        if ((threadIdx.x & 31) == 0) sw[threadIdx.x >> 5] = s;
        __syncthreads();
        if (threadIdx.x == 0) {
            float t = 0.0f;
            for (int w = 0; w < 8; w++) t += sw[w];
            g_esum[c] = t;
        }
    }
}

// ---------------- launch 3: codebook -> fp16 hi, padded rows ----------------
__global__ void vq_prepB(const float* __restrict__ emb) {
    int i = blockIdx.x * 256 + threadIdx.x;   // 288 blocks: 1024*72 = 73728
    int code = i / 72, ch = i % 72;
    float x = (ch < CDIM) ? emb[code * CDIM + ch] : 0.0f;
    g_Bh[i] = __float2half_rn(x);
}

// ---------------- launch 4: hh-MMA GEMM + top-3 + gap-gated exact re-rank ----------------
// 512 CTAs x 256 threads; CTA = 256 tokens (8 warps x 32), 8 x 128-code chunks. occ 2.
#define APADF 257
#define SM_ZF   0
#define SM_B    65792                        // 64*257*4; 2 bufs x 18432 (hi only)
#define SM_E2   102656                       // 2 x 512
#define SM_CAND 103680                       // 256 tokens x 3 x u64 = 6144
#define SM_S2   109824                       // 32
#define SMEM_TOTAL 109856

__global__ void __launch_bounds__(256, 2)
vq_main_mma(const float* __restrict__ z, const float* __restrict__ emb,
            float* __restrict__ out) {
    extern __shared__ __align__(16) char sm[];
    float* sh_zf   = (float*)(sm + SM_ZF);    // fp32 A tile [c][token], padded
    float* pS2     = (float*)(sm + SM_S2);
    u64*   sh_cand = (u64*)(sm + SM_CAND);    // [token][3] sortable (dist,idx)

    const int tid = threadIdx.x;
    const int w = tid >> 5, l = tid & 31, g = l >> 2, t = l & 3;
    const int n0 = blockIdx.x * 256;
    const int b = n0 >> 15, hwb = n0 & 32767;

    const u32 bB  = (u32)__cvta_generic_to_shared(sm + SM_B);
    const u32 bE2 = (u32)__cvta_generic_to_shared(sm + SM_E2);

#define COPY_B(o, buf) do {                                                       \
        _Pragma("unroll")                                                         \
        for (int j = 0; j < 5; j++) {                                             \
            int f = tid + 256 * j;                                                \
            if (f < 1152) {                                                       \
                const float4* src = ((const float4*)g_Bh) + (o) * 1152 + f;       \
                u32 dst = bB + (buf) * 18432 + f * 16;                            \
                asm volatile("cp.async.cg.shared.global [%0], [%1], 16;"          \
                             :: "r"(dst), "l"(src));                              \
            }                                                                     \
        }                                                                         \
        if (tid < 128) {                                                          \
            u32 de = bE2 + (buf) * 512 + tid * 4;                                 \
            asm volatile("cp.async.ca.shared.global [%0], [%1], 4;"               \
                         :: "r"(de), "l"(g_e2 + (o) * 128 + tid));                \
        }                                                                         \
        asm volatile("cp.async.commit_group;");                                   \
    } while (0)

    COPY_B(0, 0);

    // ---- A load: 256 tokens x 64 ch, fp32 into smem, fold z^2 ----
    const float* zp = z + (size_t)b * CDIM * HWD + hwb + tid;
    float s2 = 0.0f;
#pragma unroll
    for (int c = 0; c < 64; c++) {
        float x = zp[(size_t)c * HWD];
        sh_zf[c * APADF + tid] = x;
        s2 = fmaf(x, x, s2);
    }
    s2 = warp_red(s2);
    if (l == 0) pS2[w] = s2;
    __syncthreads();
    if (tid == 0) {
        float v = 0.0f;
        for (int i = 0; i < 8; i++) v += pS2[i];
        atomicAdd(&g_sz2, v);
    }
    // per-channel z sums (fp32 exact from smem)
    {
        int c = tid >> 2, q = tid & 3;
        const float* pz = sh_zf + c * APADF + q * 64;
        float s = 0.0f;
#pragma unroll
        for (int i = 0; i < 64; i++) s += pz[i];
        atomicAdd(&g_zsum[c], s);
    }

    // ---- build A fragments (fp16 hi) in registers, held for whole kernel ----
    u32 a_h[2][4][4];
    const int wb = w * 32;
#pragma unroll
    for (int m = 0; m < 2; m++) {
        int r0 = wb + m * 16 + g;
#pragma unroll
        for (int k = 0; k < 4; k++) {
            int c0 = k * 16 + 2 * t;
            a_h[m][k][0] = pack_h2(sh_zf[c0 * APADF + r0],           sh_zf[(c0 + 1) * APADF + r0]);
            a_h[m][k][1] = pack_h2(sh_zf[c0 * APADF + r0 + 8],       sh_zf[(c0 + 1) * APADF + r0 + 8]);
            a_h[m][k][2] = pack_h2(sh_zf[(c0 + 8) * APADF + r0],     sh_zf[(c0 + 9) * APADF + r0]);
            a_h[m][k][3] = pack_h2(sh_zf[(c0 + 8) * APADF + r0 + 8], sh_zf[(c0 + 9) * APADF + r0 + 8]);
        }
    }

    // per-chain top-3 (4 chains = 4 token rows per thread), traversal = ascending code
    float bd[4][3];
    int   bi[4][3];
#pragma unroll
    for (int s = 0; s < 4; s++) {
        bd[s][0] = bd[s][1] = bd[s][2] = 3.4e38f;
        bi[s][0] = bi[s][1] = bi[s][2] = 0;
    }
#define UPD3(s, d, c) do {                                                     \
        if ((d) < bd[s][2]) {                                                  \
            if ((d) < bd[s][1]) {                                              \
                bd[s][2] = bd[s][1]; bi[s][2] = bi[s][1];                      \
                if ((d) < bd[s][0]) {                                          \
                    bd[s][1] = bd[s][0]; bi[s][1] = bi[s][0];                  \
                    bd[s][0] = (d); bi[s][0] = (c);                            \
                } else { bd[s][1] = (d); bi[s][1] = (c); }                     \
            } else { bd[s][2] = (d); bi[s][2] = (c); }                         \
        }                                                                      \
    } while (0)

    // ---- main loop: 8 chunks of 128 codes, double-buffered cp.async ----
#pragma unroll 1
    for (int o = 0; o < 8; o++) {
        asm volatile("cp.async.wait_group 0;" ::: "memory");
        __syncthreads();
        if (o < 7) COPY_B(o + 1, (o + 1) & 1);

        const __half* bh  = (const __half*)(sm + SM_B + (o & 1) * 18432);
        const float*  e2p = (const float*)(sm + SM_E2 + (o & 1) * 512);

#pragma unroll 1
        for (int sub = 0; sub < 8; sub++) {           // 16 codes per sub
            u32 Bh[2][4][2];
#pragma unroll
            for (int n = 0; n < 2; n++) {
                const __half* rb = bh + (sub * 16 + n * 8 + g) * 72;
#pragma unroll
                for (int k = 0; k < 4; k++) {
                    Bh[n][k][0] = *(const u32*)(rb + k * 16 + 2 * t);
                    Bh[n][k][1] = *(const u32*)(rb + k * 16 + 2 * t + 8);
                }
            }
            float D[2][2][4] = {};
#pragma unroll
            for (int k = 0; k < 4; k++)
#pragma unroll
                for (int n = 0; n < 2; n++)
#pragma unroll
                    for (int m = 0; m < 2; m++)
                        mma16816(D[n][m], a_h[m][k], Bh[n][k]);   // hi*hi only

            // dist = e2 - 2*dot, ascending code order per chain
#pragma unroll
            for (int n = 0; n < 2; n++) {
                int cl = sub * 16 + n * 8 + 2 * t;
                float e2a = e2p[cl], e2b = e2p[cl + 1];
                int cA = o * 128 + cl;
#pragma unroll
                for (int m = 0; m < 2; m++) {
                    float d0 = fmaf(-2.0f, D[n][m][0], e2a);
                    float d1 = fmaf(-2.0f, D[n][m][1], e2b);
                    float d2 = fmaf(-2.0f, D[n][m][2], e2a);
                    float d3 = fmaf(-2.0f, D[n][m][3], e2b);
                    UPD3(m * 2, d0, cA);
                    UPD3(m * 2, d1, cA + 1);
                    UPD3(m * 2 + 1, d2, cA);
                    UPD3(m * 2 + 1, d3, cA + 1);
                }
            }
        }
    }

    // ---- quad merge: per chain, merge 4 lanes' sorted top-3 via u64 keys ----
#pragma unroll
    for (int s = 0; s < 4; s++) {
        u64 K0 = ((u64)fkey(bd[s][0]) << 32) | (u32)bi[s][0];
        u64 K1 = ((u64)fkey(bd[s][1]) << 32) | (u32)bi[s][1];
        u64 K2 = ((u64)fkey(bd[s][2]) << 32) | (u32)bi[s][2];
#pragma unroll
        for (int off = 1; off <= 2; off <<= 1) {
            u64 OA = __shfl_xor_sync(0xffffffffu, K0, off);
            u64 OB = __shfl_xor_sync(0xffffffffu, K1, off);
            u64 OC = __shfl_xor_sync(0xffffffffu, K2, off);
            u64 r0 = u64min(K0, OA);
            u64 m  = u64max(K0, OA);
            u64 c1 = u64min(K1, OB);
            u64 c1x = u64max(K1, OB);
            u64 r1 = u64min(m, c1);
            u64 r2 = u64min(u64max(m, c1), u64min(c1x, u64min(K2, OC)));
            K0 = r0; K1 = r1; K2 = r2;
        }
        if (t == 0) {
            int tok = wb + (s >> 1) * 16 + (s & 1) * 8 + g;
            sh_cand[tok * 3 + 0] = K0;
            sh_cand[tok * 3 + 1] = K1;
            sh_cand[tok * 3 + 2] = K2;
        }
    }
    __syncthreads();

    // ---- per-token: gate on approx gap, exact fp32 re-rank of top-3 if close ----
    const float4* e4 = (const float4*)emb;
    u64 K0 = sh_cand[tid * 3 + 0];
    u64 K1 = sh_cand[tid * 3 + 1];
    u64 K2 = sh_cand[tid * 3 + 2];
    int idx = (int)(K0 & 0xFFFFFFFFu);
    float ad0 = fdec((u32)(K0 >> 32));
    float ad1 = fdec((u32)(K1 >> 32));
    if (ad1 - ad0 < 0.05f) {
        int j1 = (int)(K1 & 0xFFFFFFFFu);
        int j2 = (int)(K2 & 0xFFFFFFFFu);
        float eA = exact_dist(sh_zf + tid, APADF, e4, idx);
        float eB = exact_dist(sh_zf + tid, APADF, e4, j1);
        float eC = exact_dist(sh_zf + tid, APADF, e4, j2);
        if (eB < eA || (eB == eA && j1 < idx)) { eA = eB; idx = j1; }
        if (eC < eA || (eC == eA && j2 < idx)) { idx = j2; }
    }

    // ---- per-token outputs: index, histogram, coalesced z_q gather ----
    out[IDX_OFF + n0 + tid] = (float)idx;
    atomicAdd(&g_hist[idx], 1);

    float* ob = out + (size_t)b * CDIM * HWD + hwb + tid;
#pragma unroll
    for (int j = 0; j < 16; j++) {
        float4 v = __ldg(&e4[idx * 16 + j]);
        ob[(size_t)(4 * j + 0) * HWD] = v.x;
        ob[(size_t)(4 * j + 1) * HWD] = v.y;
        ob[(size_t)(4 * j + 2) * HWD] = v.z;
        ob[(size_t)(4 * j + 3) * HWD] = v.w;
    }
#undef COPY_B
#undef UPD3
}

// ---------------- launch 5: perplexity + analytic mean(dist) ----------------
__global__ void vq_final(float* __restrict__ out) {
    int t = threadIdx.x;   // 1024 threads
    double e2  = (double)g_e2[t];
    double h   = (double)g_hist[t] * (1.0 / (double)TOKENS);
    double ent = -h * log(h + 1e-10);
    double dss = (t < CDIM) ? (double)g_zsum[t] * (double)g_esum[t] : 0.0;

    __shared__ double s1[32], s2[32], s3[32];
#pragma unroll
    for (int o = 16; o; o >>= 1) {
        e2  += __shfl_down_sync(0xffffffffu, e2,  o);
        ent += __shfl_down_sync(0xffffffffu, ent, o);
        dss += __shfl_down_sync(0xffffffffu, dss, o);
    }
    int w = t >> 5, l = t & 31;
    if (l == 0) { s1[w] = e2; s2[w] = ent; s3[w] = dss; }
    __syncthreads();
    if (t == 0) {
        double E2 = 0, EN = 0, DS = 0;
        for (int i = 0; i < 32; i++) { E2 += s1[i]; EN += s2[i]; DS += s3[i]; }
        out[LOSS_OFF] = 0.0f;
        out[PERP_OFF] = (float)exp(EN);
        double nt = (double)TOKENS, kk = (double)KCODES;
        out[MEAN_OFF] = (float)((kk * (double)g_sz2 - 2.0 * DS + nt * E2) / (nt * kk));
    }
}

extern "C" void kernel_launch(void* const* d_in, const int* in_sizes, int n_in,
                              void* d_out, int out_size) {
    (void)in_sizes; (void)n_in; (void)out_size;
    const float* z   = (const float*)d_in[0];
    const float* emb = (const float*)d_in[1];
    float* out = (float*)d_out;

    cudaFuncSetAttribute(vq_main_mma, cudaFuncAttributeMaxDynamicSharedMemorySize, SMEM_TOTAL);

    vq_init    <<<1,   1024>>>();                       // 1
    vq_prep1   <<<68,  256 >>>(emb);                    // 2
    vq_prepB   <<<288, 256 >>>(emb);                    // 3
    vq_main_mma<<<512, 256, SMEM_TOTAL>>>(z, emb, out); // 4 (ncu captures this)
    vq_final   <<<1,   1024>>>(out);                    // 5
}

// round 7
// speedup vs baseline: 3.7349x; 1.3174x over previous
#include <cuda_runtime.h>
#include <cuda_fp16.h>
#include <cstdint>
#include <math.h>

// ---------------- problem constants ----------------
#define TOKENS   131072      // 4 * 32 * 32 * 32
#define CDIM     64
#define KCODES   1024
#define HWD      32768
// out layout: [z_q (8388608) | loss | perplexity | indices (131072) | mean_dist]
#define LOSS_OFF 8388608
#define PERP_OFF 8388609
#define IDX_OFF  8388610
#define MEAN_OFF 8519682

#define DBIAS 512.0f         // positivity bias for packed keys

typedef unsigned int u32;

// ---------------- global scratch (static, no allocs) ----------------
__device__ float g_e2[KCODES];          // ||e_k||^2 (raw, for exact re-rank)
__device__ float g_e2b[KCODES];         // ||e_k||^2 + DBIAS (for packed keys)
__device__ float g_esum[CDIM];          // sum_k e[k][c]
__device__ float g_zsum[CDIM];          // sum_n z[n][c]
__device__ float g_sz2;                 // sum all z^2
__device__ int   g_hist[KCODES];        // argmin bincount
// codebook fp16 in per-lane mma fragment order: [chunk8][sub8][q4][lane32][4xu32]
__device__ __align__(16) u32 g_Bf[65536];

// ---------------- helpers ----------------
__device__ __forceinline__ float warp_red(float v) {
#pragma unroll
    for (int o = 16; o; o >>= 1) v += __shfl_down_sync(0xffffffffu, v, o);
    return v;
}
__device__ __forceinline__ u32 pack_h2(float x0, float x1) {
    __half2 h = __halves2half2(__float2half_rn(x0), __float2half_rn(x1));
    return *reinterpret_cast<u32*>(&h);
}
// m16n8k16 row.col f16 -> f32 accumulate (HMMA)
__device__ __forceinline__ void mma16816(float d[4], const u32 a[4], u32 b0, u32 b1) {
    asm("mma.sync.aligned.m16n8k16.row.col.f32.f16.f16.f32 "
        "{%0,%1,%2,%3}, {%4,%5,%6,%7}, {%8,%9}, {%0,%1,%2,%3};"
        : "+f"(d[0]), "+f"(d[1]), "+f"(d[2]), "+f"(d[3])
        : "r"(a[0]), "r"(a[1]), "r"(a[2]), "r"(a[3]), "r"(b0), "r"(b1));
}

// exact fp32 distance with ROUND-1 accumulation order (matches reference):
// 4 accumulators by channel mod 4, merged (A0+A1)+(A2+A3), dist = fma(-2, dot, e2)
__device__ __forceinline__ float exact_dist(const float* __restrict__ zcol, int apad,
                                            const float4* __restrict__ e4, int code) {
    float A0 = 0.0f, A1 = 0.0f, A2 = 0.0f, A3 = 0.0f;
#pragma unroll
    for (int c4 = 0; c4 < 16; c4++) {
        float4 e = __ldg(&e4[code * 16 + c4]);
        A0 = fmaf(zcol[(4 * c4 + 0) * apad], e.x, A0);
        A1 = fmaf(zcol[(4 * c4 + 1) * apad], e.y, A1);
        A2 = fmaf(zcol[(4 * c4 + 2) * apad], e.z, A2);
        A3 = fmaf(zcol[(4 * c4 + 3) * apad], e.w, A3);
    }
    float dot = (A0 + A1) + (A2 + A3);
    return fmaf(-2.0f, dot, g_e2[code]);
}

// ---------------- launch 1: init ----------------
__global__ void vq_init() {
    int t = threadIdx.x;            // 1024 threads
    g_hist[t] = 0;
    if (t < CDIM) g_zsum[t] = 0.0f;
    if (t == 0)   g_sz2 = 0.0f;
}

// ---------------- launch 2: e2/e2b (blocks 0-3) + esum (blocks 4-67) ----------------
__global__ void vq_prep1(const float* __restrict__ emb) {
    if (blockIdx.x < 4) {
        int k = blockIdx.x * 256 + threadIdx.x;
        const float4* e4 = (const float4*)emb;
        float s = 0.0f;
#pragma unroll
        for (int j = 0; j < 16; j++) {
            float4 v = e4[k * 16 + j];
            s += v.x * v.x + v.y * v.y + v.z * v.z + v.w * v.w;
        }
        g_e2[k]  = s;
        g_e2b[k] = s + DBIAS;
    } else {
        int c = blockIdx.x - 4;
        float s = 0.0f;
        for (int k = threadIdx.x; k < KCODES; k += 256) s += emb[k * CDIM + c];
        s = warp_red(s);
        __shared__ float sw[8];
        if ((threadIdx.x & 31) == 0) sw[threadIdx.x >> 5] = s;
        __syncthreads();
        if (threadIdx.x == 0) {
            float t = 0.0f;
            for (int w = 0; w < 8; w++) t += sw[w];
            g_esum[c] = t;
        }
    }
}

// ---------------- launch 3: codebook -> fp16 fragment-order layout ----------------
// u = ((o*8+s)*4+q)*128 + l*4 + j ; value = halves{ E[code][ch], E[code][ch+1] }
// n=q>>1, kp=q&1, k=2kp+(j>>1), r=j&1, g=l>>2, t=l&3
// code = o*128 + s*16 + n*8 + g ; ch = k*16 + 2t + 8r
__global__ void vq_prepB(const float* __restrict__ emb) {
    u32 u = blockIdx.x * 256 + threadIdx.x;   // 256 blocks
    u32 j = u & 3, l = (u >> 2) & 31, q = (u >> 7) & 3, s = (u >> 9) & 7, o = u >> 12;
    u32 g = l >> 2, t = l & 3, n = q >> 1, kp = q & 1, k = 2 * kp + (j >> 1), r = j & 1;
    u32 code = o * 128 + s * 16 + n * 8 + g;
    u32 ch   = k * 16 + 2 * t + 8 * r;
    const float* row = emb + code * CDIM + ch;
    g_Bf[u] = pack_h2(row[0], row[1]);
}

// ---------------- launch 4: hh-MMA GEMM + packed-key top-3 + exact re-rank ----------------
// 512 CTAs x 256 threads; CTA = 256 tokens (8 warps x 32), 8 x 128-code chunks. occ 2.
#define APADF 257
#define SM_ZF   0
#define SM_B    65792                        // 2 bufs x 16384 (fragment-order fp16)
#define SM_E2   98560                        // 2 x 512 (biased e2)
#define SM_CAND 99584                        // 256 tokens x 3 x u32 = 3072
#define SM_S2   102656                       // 32
#define SMEM_TOTAL 102688

__global__ void __launch_bounds__(256, 2)
vq_main_mma(const float* __restrict__ z, const float* __restrict__ emb,
            float* __restrict__ out) {
    extern __shared__ __align__(16) char sm[];
    float* sh_zf   = (float*)(sm + SM_ZF);    // fp32 A tile [c][token], padded
    float* pS2     = (float*)(sm + SM_S2);
    u32*   sh_cand = (u32*)(sm + SM_CAND);    // [token][3] packed (dist|code)

    const int tid = threadIdx.x;
    const int w = tid >> 5, l = tid & 31, g = l >> 2, t = l & 3;
    const int n0 = blockIdx.x * 256;
    const int b = n0 >> 15, hwb = n0 & 32767;

    const u32 bB  = (u32)__cvta_generic_to_shared(sm + SM_B);
    const u32 bE2 = (u32)__cvta_generic_to_shared(sm + SM_E2);

#define COPY_B(o, buf) do {                                                       \
        _Pragma("unroll")                                                         \
        for (int j = 0; j < 4; j++) {                                             \
            int f = tid + 256 * j;                                                \
            const float4* src = ((const float4*)g_Bf) + (o) * 1024 + f;           \
            u32 dst = bB + (buf) * 16384 + f * 16;                                \
            asm volatile("cp.async.cg.shared.global [%0], [%1], 16;"              \
                         :: "r"(dst), "l"(src));                                  \
        }                                                                         \
        if (tid < 128) {                                                          \
            u32 de = bE2 + (buf) * 512 + tid * 4;                                 \
            asm volatile("cp.async.ca.shared.global [%0], [%1], 4;"               \
                         :: "r"(de), "l"(g_e2b + (o) * 128 + tid));               \
        }                                                                         \
        asm volatile("cp.async.commit_group;");                                   \
    } while (0)

    COPY_B(0, 0);

    // ---- A load: 256 tokens x 64 ch, fp32 into smem, fold z^2 ----
    const float* zp = z + (size_t)b * CDIM * HWD + hwb + tid;
    float s2 = 0.0f;
#pragma unroll
    for (int c = 0; c < 64; c++) {
        float x = zp[(size_t)c * HWD];
        sh_zf[c * APADF + tid] = x;
        s2 = fmaf(x, x, s2);
    }
    s2 = warp_red(s2);
    if (l == 0) pS2[w] = s2;
    __syncthreads();
    if (tid == 0) {
        float v = 0.0f;
        for (int i = 0; i < 8; i++) v += pS2[i];
        atomicAdd(&g_sz2, v);
    }
    // per-channel z sums (fp32 exact from smem)
    {
        int c = tid >> 2, q = tid & 3;
        const float* pz = sh_zf + c * APADF + q * 64;
        float s = 0.0f;
#pragma unroll
        for (int i = 0; i < 64; i++) s += pz[i];
        atomicAdd(&g_zsum[c], s);
    }

    // ---- build A fragments (fp16) in registers, held for whole kernel ----
    u32 a_h[2][4][4];
    const int wb = w * 32;
#pragma unroll
    for (int m = 0; m < 2; m++) {
        int r0 = wb + m * 16 + g;
#pragma unroll
        for (int k = 0; k < 4; k++) {
            int c0 = k * 16 + 2 * t;
            a_h[m][k][0] = pack_h2(sh_zf[c0 * APADF + r0],           sh_zf[(c0 + 1) * APADF + r0]);
            a_h[m][k][1] = pack_h2(sh_zf[c0 * APADF + r0 + 8],       sh_zf[(c0 + 1) * APADF + r0 + 8]);
            a_h[m][k][2] = pack_h2(sh_zf[(c0 + 8) * APADF + r0],     sh_zf[(c0 + 9) * APADF + r0]);
            a_h[m][k][3] = pack_h2(sh_zf[(c0 + 8) * APADF + r0 + 8], sh_zf[(c0 + 9) * APADF + r0 + 8]);
        }
    }

    // per-chain top-3 packed keys (4 chains = 4 token rows per thread)
    u32 K0a[4], K1a[4], K2a[4];
#pragma unroll
    for (int s = 0; s < 4; s++) { K0a[s] = K1a[s] = K2a[s] = 0xFFFFFFFFu; }
    // branchless sorted-insert of x into (K0<=K1<=K2): 5 IMNMX
#define INS3(s, x) do {                                                        \
        u32 _m = min(K0a[s], (x));                                             \
        u32 _M = max(K0a[s], (x));                                             \
        K0a[s] = _m;                                                           \
        u32 _m2 = min(K1a[s], _M);                                             \
        _M = max(K1a[s], _M);                                                  \
        K1a[s] = _m2;                                                          \
        K2a[s] = min(K2a[s], _M);                                              \
    } while (0)
#define MKKEY(d, c) ((__float_as_uint(d) & 0xFFFFFC00u) | (u32)(c))

    // ---- main loop: 8 chunks of 128 codes, double-buffered cp.async ----
#pragma unroll 1
    for (int o = 0; o < 8; o++) {
        asm volatile("cp.async.wait_group 0;" ::: "memory");
        __syncthreads();
        if (o < 7) COPY_B(o + 1, (o + 1) & 1);

        const char*  bbase = sm + SM_B + (o & 1) * 16384;
        const float* e2p   = (const float*)(sm + SM_E2 + (o & 1) * 512);

#pragma unroll 1
        for (int sub = 0; sub < 8; sub++) {           // 16 codes per sub
            const uint4* bp = (const uint4*)(bbase + sub * 2048 + l * 16);
            uint4 q0 = bp[0];     // n=0, k=0..1
            uint4 q1 = bp[32];    // n=0, k=2..3
            uint4 q2 = bp[64];    // n=1, k=0..1
            uint4 q3 = bp[96];    // n=1, k=2..3

            float D[2][2][4] = {};
#pragma unroll
            for (int m = 0; m < 2; m++) {
                mma16816(D[0][m], a_h[m][0], q0.x, q0.y);
                mma16816(D[0][m], a_h[m][1], q0.z, q0.w);
                mma16816(D[0][m], a_h[m][2], q1.x, q1.y);
                mma16816(D[0][m], a_h[m][3], q1.z, q1.w);
                mma16816(D[1][m], a_h[m][0], q2.x, q2.y);
                mma16816(D[1][m], a_h[m][1], q2.z, q2.w);
                mma16816(D[1][m], a_h[m][2], q3.x, q3.y);
                mma16816(D[1][m], a_h[m][3], q3.z, q3.w);
            }

            // dist = e2b - 2*dot (biased positive), pack code, branchless top-3
            int cbase = o * 128 + sub * 16 + 2 * t;
#pragma unroll
            for (int n = 0; n < 2; n++) {
                int cc = cbase + n * 8;
                float e2a = e2p[sub * 16 + n * 8 + 2 * t];
                float e2b = e2p[sub * 16 + n * 8 + 2 * t + 1];
#pragma unroll
                for (int m = 0; m < 2; m++) {
                    float d0 = fmaf(-2.0f, D[n][m][0], e2a);
                    float d1 = fmaf(-2.0f, D[n][m][1], e2b);
                    float d2 = fmaf(-2.0f, D[n][m][2], e2a);
                    float d3 = fmaf(-2.0f, D[n][m][3], e2b);
                    INS3(m * 2,     MKKEY(d0, cc));
                    INS3(m * 2,     MKKEY(d1, cc + 1));
                    INS3(m * 2 + 1, MKKEY(d2, cc));
                    INS3(m * 2 + 1, MKKEY(d3, cc + 1));
                }
            }
        }
    }

    // ---- quad merge: per chain, merge 4 lanes' sorted top-3 (u32 keys) ----
#pragma unroll
    for (int s = 0; s < 4; s++) {
        u32 K0 = K0a[s], K1 = K1a[s], K2 = K2a[s];
#pragma unroll
        for (int off = 1; off <= 2; off <<= 1) {
            u32 OA = __shfl_xor_sync(0xffffffffu, K0, off);
            u32 OB = __shfl_xor_sync(0xffffffffu, K1, off);
            u32 OC = __shfl_xor_sync(0xffffffffu, K2, off);
            u32 r0  = min(K0, OA);
            u32 m   = max(K0, OA);
            u32 c1  = min(K1, OB);
            u32 c1x = max(K1, OB);
            u32 r1  = min(m, c1);
            u32 r2  = min(max(m, c1), min(c1x, min(K2, OC)));
            K0 = r0; K1 = r1; K2 = r2;
        }
        if (t == 0) {
            int tok = wb + (s >> 1) * 16 + (s & 1) * 8 + g;
            sh_cand[tok * 3 + 0] = K0;
            sh_cand[tok * 3 + 1] = K1;
            sh_cand[tok * 3 + 2] = K2;
        }
    }
    __syncthreads();

    // ---- per-token: gate on approx gap, exact fp32 re-rank of top-3 if close ----
    const float4* e4 = (const float4*)emb;
    u32 K0 = sh_cand[tid * 3 + 0];
    u32 K1 = sh_cand[tid * 3 + 1];
    u32 K2 = sh_cand[tid * 3 + 2];
    int idx = (int)(K0 & 1023u);
    float ad0 = __uint_as_float(K0 & 0xFFFFFC00u);
    float ad1 = __uint_as_float(K1 & 0xFFFFFC00u);
    if (ad1 - ad0 < 0.25f) {     // gate >> fp16 err (~0.03 max) + 2x pack err (0.125)
        int j1 = (int)(K1 & 1023u);
        int j2 = (int)(K2 & 1023u);
        float eA = exact_dist(sh_zf + tid, APADF, e4, idx);
        float eB = exact_dist(sh_zf + tid, APADF, e4, j1);
        float eC = exact_dist(sh_zf + tid, APADF, e4, j2);
        if (eB < eA || (eB == eA && j1 < idx)) { eA = eB; idx = j1; }
        if (eC < eA || (eC == eA && j2 < idx)) { idx = j2; }
    }

    // ---- per-token outputs: index, histogram, coalesced z_q gather ----
    out[IDX_OFF + n0 + tid] = (float)idx;
    atomicAdd(&g_hist[idx], 1);

    float* ob = out + (size_t)b * CDIM * HWD + hwb + tid;
#pragma unroll
    for (int j = 0; j < 16; j++) {
        float4 v = __ldg(&e4[idx * 16 + j]);
        ob[(size_t)(4 * j + 0) * HWD] = v.x;
        ob[(size_t)(4 * j + 1) * HWD] = v.y;
        ob[(size_t)(4 * j + 2) * HWD] = v.z;
        ob[(size_t)(4 * j + 3) * HWD] = v.w;
    }
#undef COPY_B
#undef INS3
#undef MKKEY
}

// ---------------- launch 5: perplexity + analytic mean(dist) ----------------
__global__ void vq_final(float* __restrict__ out) {
    int t = threadIdx.x;   // 1024 threads
    double e2  = (double)g_e2[t];
    double h   = (double)g_hist[t] * (1.0 / (double)TOKENS);
    double ent = -h * log(h + 1e-10);
    double dss = (t < CDIM) ? (double)g_zsum[t] * (double)g_esum[t] : 0.0;

    __shared__ double s1[32], s2[32], s3[32];
#pragma unroll
    for (int o = 16; o; o >>= 1) {
        e2  += __shfl_down_sync(0xffffffffu, e2,  o);
        ent += __shfl_down_sync(0xffffffffu, ent, o);
        dss += __shfl_down_sync(0xffffffffu, dss, o);
    }
    int w = t >> 5, l = t & 31;
    if (l == 0) { s1[w] = e2; s2[w] = ent; s3[w] = dss; }
    __syncthreads();
    if (t == 0) {
        double E2 = 0, EN = 0, DS = 0;
        for (int i = 0; i < 32; i++) { E2 += s1[i]; EN += s2[i]; DS += s3[i]; }
        out[LOSS_OFF] = 0.0f;
        out[PERP_OFF] = (float)exp(EN);
        double nt = (double)TOKENS, kk = (double)KCODES;
        out[MEAN_OFF] = (float)((kk * (double)g_sz2 - 2.0 * DS + nt * E2) / (nt * kk));
    }
}

extern "C" void kernel_launch(void* const* d_in, const int* in_sizes, int n_in,
                              void* d_out, int out_size) {
    (void)in_sizes; (void)n_in; (void)out_size;
    const float* z   = (const float*)d_in[0];
    const float* emb = (const float*)d_in[1];
    float* out = (float*)d_out;

    cudaFuncSetAttribute(vq_main_mma, cudaFuncAttributeMaxDynamicSharedMemorySize, SMEM_TOTAL);

    vq_init    <<<1,   1024>>>();                       // 1
    vq_prep1   <<<68,  256 >>>(emb);                    // 2
    vq_prepB   <<<256, 256 >>>(emb);                    // 3
    vq_main_mma<<<512, 256, SMEM_TOTAL>>>(z, emb, out); // 4 (ncu captures this)
    vq_final   <<<1,   1024>>>(out);                    // 5
}